// round 9
// baseline (speedup 1.0000x reference)
#include <cuda_runtime.h>
#include <cuda_bf16.h>
#include <cstdint>

#define NMAX 50000
#define EMAX 800000
#define D 128
#define D4 32
#define BN_EPS 1e-5f
#define SCAN_BLK 1024
#define SCAN_NB  49
#define PITCH 272            // bytes per 128-bf16 row (256 + 16 pad)

// ---------------- scratch ----------------
__device__ float4 g_agg[NMAX * D4];
__device__ int    g_deg_out[NMAX];
__device__ int    g_deg_in[NMAX];
__device__ int    g_incl[SCAN_NB * SCAN_BLK];
__device__ int    g_bsum[SCAN_NB];
__device__ int    g_rowstart[NMAX];
__device__ int    g_cursor[NMAX];
__device__ int    g_csrc[EMAX];
__device__ float  g_inv_in[NMAX];
__device__ float  g_inv_out[NMAX];
__device__ float  g_sum[D];
__device__ float  g_sq[D];
__device__ float  g_scale[D];
__device__ float  g_shift[D];
// pre-split weights, [n][k] layout (k contiguous, 256B per n-row)
__device__ __nv_bfloat16 g_Whi[16384], g_Wlo[16384], g_Wrhi[16384], g_Wrlo[16384];

// ---------------- helpers ----------------
__device__ __forceinline__ uint32_t smem_u32(const void* p) {
    uint32_t a;
    asm("{ .reg .u64 t; cvta.to.shared.u64 t, %1; cvt.u32.u64 %0, t; }" : "=r"(a) : "l"(p));
    return a;
}
__device__ __forceinline__ uint32_t lds32(uint32_t a) {
    uint32_t v;
    asm volatile("ld.shared.b32 %0, [%1];" : "=r"(v) : "r"(a));
    return v;
}
__device__ __forceinline__ void sts128(uint32_t a, uint4 v) {
    asm volatile("st.shared.v4.b32 [%0], {%1,%2,%3,%4};"
                 :: "r"(a), "r"(v.x), "r"(v.y), "r"(v.z), "r"(v.w) : "memory");
}
__device__ __forceinline__ void mma_bf16(float* d, const uint32_t* a, uint32_t b0, uint32_t b1) {
    asm volatile(
        "mma.sync.aligned.m16n8k16.row.col.f32.bf16.bf16.f32 "
        "{%0,%1,%2,%3}, {%4,%5,%6,%7}, {%8,%9}, {%0,%1,%2,%3};"
        : "+f"(d[0]), "+f"(d[1]), "+f"(d[2]), "+f"(d[3])
        : "r"(a[0]), "r"(a[1]), "r"(a[2]), "r"(a[3]), "r"(b0), "r"(b1));
}
__device__ __forceinline__ void splitstore(float v, __nv_bfloat16* hi, __nv_bfloat16* lo) {
    __nv_bfloat16 h = __float2bfloat16_rn(v);
    *hi = h;
    *lo = __float2bfloat16_rn(v - __bfloat162float(h));
}

// ---------------- 1) zero ----------------
__global__ void zero_kernel(int N) {
    int i = blockIdx.x * blockDim.x + threadIdx.x;
    if (i < N) { g_deg_out[i] = 0; g_deg_in[i] = 0; }
    if (i < D) { g_sum[i] = 0.f; g_sq[i] = 0.f; }
}

// ---------------- 2) degrees ----------------
__global__ void degree_kernel(const int* __restrict__ src,
                              const int* __restrict__ dst, int nE) {
    int e = blockIdx.x * blockDim.x + threadIdx.x;
    if (e < nE) {
        atomicAdd(&g_deg_out[src[e]], 1);
        atomicAdd(&g_deg_in[dst[e]], 1);
    }
}

// ---------------- 3a) per-block inclusive scan (warp-shuffle) ----------------
__global__ void scan1_kernel(int N) {
    __shared__ int wsum[32];
    int t = threadIdx.x, lane = t & 31, w = t >> 5;
    int i = blockIdx.x * SCAN_BLK + t;
    int v = (i < N) ? g_deg_in[i] : 0;
    int s = v;
    #pragma unroll
    for (int off = 1; off < 32; off <<= 1) {
        int u = __shfl_up_sync(0xffffffffu, s, off);
        if (lane >= off) s += u;
    }
    if (lane == 31) wsum[w] = s;
    __syncthreads();
    if (w == 0) {
        int ws = wsum[lane];
        #pragma unroll
        for (int off = 1; off < 32; off <<= 1) {
            int u = __shfl_up_sync(0xffffffffu, ws, off);
            if (lane >= off) ws += u;
        }
        wsum[lane] = ws;
    }
    __syncthreads();
    int add = (w > 0) ? wsum[w - 1] : 0;
    g_incl[i] = s + add;
    if (t == SCAN_BLK - 1) g_bsum[blockIdx.x] = s + add;
}

// ---------------- 3b) finalize (block offset inline) ----------------
__global__ void scan3_kernel(int N) {
    __shared__ int s_off;
    if (threadIdx.x < 32) {
        int lane = threadIdx.x;
        int v = 0;
        if (lane < blockIdx.x) v += g_bsum[lane];
        int l2 = lane + 32;
        if (l2 < SCAN_NB && l2 < blockIdx.x) v += g_bsum[l2];
        #pragma unroll
        for (int off = 16; off > 0; off >>= 1)
            v += __shfl_down_sync(0xffffffffu, v, off);
        if (lane == 0) s_off = v;
    }
    __syncthreads();
    int i = blockIdx.x * SCAN_BLK + threadIdx.x;
    if (i >= N) return;
    int din = g_deg_in[i];
    int rs = g_incl[i] - din + s_off;
    g_rowstart[i] = rs;
    g_cursor[i]   = rs;
    g_inv_in[i]  = rsqrtf(fmaxf((float)din, 1.f));
    g_inv_out[i] = rsqrtf(fmaxf((float)g_deg_out[i], 1.f));
}

// ---------------- 4) CSR fill ----------------
__global__ void fill_kernel(const int* __restrict__ src,
                            const int* __restrict__ dst, int nE) {
    int e = blockIdx.x * blockDim.x + threadIdx.x;
    if (e < nE) {
        int pos = atomicAdd(&g_cursor[dst[e]], 1);
        g_csrc[pos] = src[e];
    }
}

// ---------------- 5) gather ----------------
__global__ void gather_kernel(const float4* __restrict__ x4, int N) {
    int w = (blockIdx.x * blockDim.x + threadIdx.x) >> 5;
    int lane = threadIdx.x & 31;
    if (w >= N) return;
    int start = g_rowstart[w];
    int deg   = g_deg_in[w];
    float4 acc = make_float4(0.f, 0.f, 0.f, 0.f);
    for (int base = 0; base < deg; base += 32) {
        int rem = deg - base;
        int cnt = rem < 32 ? rem : 32;
        int sIdx = 0;
        if (lane < cnt) sIdx = g_csrc[start + base + lane];
        #pragma unroll 4
        for (int j = 0; j < cnt; j++) {
            int s = __shfl_sync(0xffffffffu, sIdx, j);
            float sc = __ldg(&g_inv_out[s]);
            float4 v = x4[s * D4 + lane];
            acc.x = fmaf(v.x, sc, acc.x);
            acc.y = fmaf(v.y, sc, acc.y);
            acc.z = fmaf(v.z, sc, acc.z);
            acc.w = fmaf(v.w, sc, acc.w);
        }
    }
    float inv = g_inv_in[w];
    acc.x *= inv; acc.y *= inv; acc.z *= inv; acc.w *= inv;
    g_agg[w * D4 + lane] = acc;
}

// ---------------- 6) prep weights ----------------
__global__ void prepw_kernel(const float* __restrict__ W, const float* __restrict__ Wr) {
    int t = blockIdx.x * blockDim.x + threadIdx.x;
    if (t >= 16384) return;
    int k = t & 127;
    int n = t >> 7;
    int idx = n * 128 + k;
    splitstore(W[k * D + n],  &g_Whi[idx],  &g_Wlo[idx]);
    splitstore(Wr[k * D + n], &g_Wrhi[idx], &g_Wrlo[idx]);
}

// ---------------- 7) HMMA dual GEMM, 64x128 tile, B frags via LDG -------------
// 8 warps at 32x32; A (agg & x, hi/lo) in smem (4 x 17KB); weights from L1.
__global__ void __launch_bounds__(256, 2)
gemm_mma_kernel(const float4* __restrict__ x4,
                const float* __restrict__ b, const float* __restrict__ br,
                float* __restrict__ y, int N) {
    extern __shared__ char dsm[];
    uint32_t base = smem_u32(dsm);
    const uint32_t AG_HI = base,           AG_LO = base + 17408u;
    const uint32_t AX_HI = base + 34816u,  AX_LO = base + 52224u;

    __shared__ float sb[D], sbr[D];

    int tid = threadIdx.x;
    int lane = tid & 31, warp = tid >> 5;
    int gID = lane >> 2, tig = lane & 3;
    int warpRow = (warp & 1) * 32;      // 0,32
    int warpCol = (warp >> 1) * 32;     // 0,32,64,96
    int rowbase = blockIdx.x * 64;

    if (tid < D) { sb[tid] = b[tid]; sbr[tid] = br[tid]; }

    // ---- load both A tiles (agg and x), split hi/lo ----
    #pragma unroll
    for (int i = tid; i < 1024; i += 256) {
        int row = i >> 4, ch = i & 15;
        int gr = rowbase + row;
        float4 a0 = make_float4(0.f,0.f,0.f,0.f), a1 = a0, v0 = a0, v1 = a0;
        if (gr < N) {
            a0 = g_agg[gr * D4 + ch * 2]; a1 = g_agg[gr * D4 + ch * 2 + 1];
            v0 = x4[gr * D4 + ch * 2];    v1 = x4[gr * D4 + ch * 2 + 1];
        }
        __nv_bfloat16 hi[8], lo[8];
        uint32_t off = (uint32_t)row * PITCH + (uint32_t)ch * 16;
        splitstore(a0.x, hi+0, lo+0); splitstore(a0.y, hi+1, lo+1);
        splitstore(a0.z, hi+2, lo+2); splitstore(a0.w, hi+3, lo+3);
        splitstore(a1.x, hi+4, lo+4); splitstore(a1.y, hi+5, lo+5);
        splitstore(a1.z, hi+6, lo+6); splitstore(a1.w, hi+7, lo+7);
        sts128(AG_HI + off, *(const uint4*)hi);
        sts128(AG_LO + off, *(const uint4*)lo);
        splitstore(v0.x, hi+0, lo+0); splitstore(v0.y, hi+1, lo+1);
        splitstore(v0.z, hi+2, lo+2); splitstore(v0.w, hi+3, lo+3);
        splitstore(v1.x, hi+4, lo+4); splitstore(v1.y, hi+5, lo+5);
        splitstore(v1.z, hi+6, lo+6); splitstore(v1.w, hi+7, lo+7);
        sts128(AX_HI + off, *(const uint4*)hi);
        sts128(AX_LO + off, *(const uint4*)lo);
    }
    __syncthreads();

    float accG[2][4][4], accR[2][4][4];
    #pragma unroll
    for (int rt = 0; rt < 2; rt++)
        #pragma unroll
        for (int nt = 0; nt < 4; nt++)
            #pragma unroll
            for (int j = 0; j < 4; j++) { accG[rt][nt][j] = 0.f; accR[rt][nt][j] = 0.f; }

    // ---- phase 1: G = agg @ W ----
    #pragma unroll
    for (int ks = 0; ks < 8; ks++) {
        uint32_t kb = (uint32_t)(ks * 32 + tig * 4);
        uint32_t ahi[2][4], alo[2][4];
        #pragma unroll
        for (int rt = 0; rt < 2; rt++) {
            uint32_t b0 = (uint32_t)(warpRow + rt * 16 + gID) * PITCH + kb;
            ahi[rt][0] = lds32(AG_HI + b0);
            ahi[rt][1] = lds32(AG_HI + b0 + 8 * PITCH);
            ahi[rt][2] = lds32(AG_HI + b0 + 16);
            ahi[rt][3] = lds32(AG_HI + b0 + 8 * PITCH + 16);
            alo[rt][0] = lds32(AG_LO + b0);
            alo[rt][1] = lds32(AG_LO + b0 + 8 * PITCH);
            alo[rt][2] = lds32(AG_LO + b0 + 16);
            alo[rt][3] = lds32(AG_LO + b0 + 8 * PITCH + 16);
        }
        #pragma unroll
        for (int nt = 0; nt < 4; nt++) {
            int n0 = warpCol + nt * 8 + gID;
            const uint32_t* WH = (const uint32_t*)((const char*)g_Whi + n0 * 256 + kb);
            const uint32_t* WL = (const uint32_t*)((const char*)g_Wlo + n0 * 256 + kb);
            uint32_t bh0 = __ldg(WH), bh1 = __ldg(WH + 4);
            uint32_t bl0 = __ldg(WL), bl1 = __ldg(WL + 4);
            #pragma unroll
            for (int rt = 0; rt < 2; rt++) {
                mma_bf16(accG[rt][nt], ahi[rt], bh0, bh1);
                mma_bf16(accG[rt][nt], ahi[rt], bl0, bl1);
                mma_bf16(accG[rt][nt], alo[rt], bh0, bh1);
            }
        }
    }

    // ---- phase 2: R = x @ Wr ----
    #pragma unroll
    for (int ks = 0; ks < 8; ks++) {
        uint32_t kb = (uint32_t)(ks * 32 + tig * 4);
        uint32_t ahi[2][4], alo[2][4];
        #pragma unroll
        for (int rt = 0; rt < 2; rt++) {
            uint32_t b0 = (uint32_t)(warpRow + rt * 16 + gID) * PITCH + kb;
            ahi[rt][0] = lds32(AX_HI + b0);
            ahi[rt][1] = lds32(AX_HI + b0 + 8 * PITCH);
            ahi[rt][2] = lds32(AX_HI + b0 + 16);
            ahi[rt][3] = lds32(AX_HI + b0 + 8 * PITCH + 16);
            alo[rt][0] = lds32(AX_LO + b0);
            alo[rt][1] = lds32(AX_LO + b0 + 8 * PITCH);
            alo[rt][2] = lds32(AX_LO + b0 + 16);
            alo[rt][3] = lds32(AX_LO + b0 + 8 * PITCH + 16);
        }
        #pragma unroll
        for (int nt = 0; nt < 4; nt++) {
            int n0 = warpCol + nt * 8 + gID;
            const uint32_t* WH = (const uint32_t*)((const char*)g_Wrhi + n0 * 256 + kb);
            const uint32_t* WL = (const uint32_t*)((const char*)g_Wrlo + n0 * 256 + kb);
            uint32_t bh0 = __ldg(WH), bh1 = __ldg(WH + 4);
            uint32_t bl0 = __ldg(WL), bl1 = __ldg(WL + 4);
            #pragma unroll
            for (int rt = 0; rt < 2; rt++) {
                mma_bf16(accR[rt][nt], ahi[rt], bh0, bh1);
                mma_bf16(accR[rt][nt], ahi[rt], bl0, bl1);
                mma_bf16(accR[rt][nt], alo[rt], bh0, bh1);
            }
        }
    }

    // ---- epilogue: y = relu(G+b) + relu(R+br) ----
    #pragma unroll
    for (int rt = 0; rt < 2; rt++) {
        int gr0 = rowbase + warpRow + rt * 16 + gID;
        int gr1 = gr0 + 8;
        #pragma unroll
        for (int nt = 0; nt < 4; nt++) {
            int c0 = warpCol + nt * 8 + tig * 2;
            float bx = sb[c0], by = sb[c0 + 1];
            float brx = sbr[c0], bry = sbr[c0 + 1];
            if (gr0 < N) {
                float2 o;
                o.x = fmaxf(accG[rt][nt][0] + bx, 0.f) + fmaxf(accR[rt][nt][0] + brx, 0.f);
                o.y = fmaxf(accG[rt][nt][1] + by, 0.f) + fmaxf(accR[rt][nt][1] + bry, 0.f);
                *(float2*)(y + gr0 * D + c0) = o;
            }
            if (gr1 < N) {
                float2 o;
                o.x = fmaxf(accG[rt][nt][2] + bx, 0.f) + fmaxf(accR[rt][nt][2] + brx, 0.f);
                o.y = fmaxf(accG[rt][nt][3] + by, 0.f) + fmaxf(accR[rt][nt][3] + bry, 0.f);
                *(float2*)(y + gr1 * D + c0) = o;
            }
        }
    }
}

// ---------------- 8) BN column sums ----------------
__global__ void bnsum_kernel(const float4* __restrict__ y4, int N) {
    int q = threadIdx.x & 31, rg = threadIdx.x >> 5;
    float4 s  = make_float4(0.f,0.f,0.f,0.f);
    float4 ss = make_float4(0.f,0.f,0.f,0.f);
    for (int r = blockIdx.x * 8 + rg; r < N; r += gridDim.x * 8) {
        float4 v = y4[r * D4 + q];
        s.x += v.x; s.y += v.y; s.z += v.z; s.w += v.w;
        ss.x += v.x*v.x; ss.y += v.y*v.y; ss.z += v.z*v.z; ss.w += v.w*v.w;
    }
    __shared__ float shS[8][D], shQ[8][D];
    shS[rg][q*4+0] = s.x;  shS[rg][q*4+1] = s.y;  shS[rg][q*4+2] = s.z;  shS[rg][q*4+3] = s.w;
    shQ[rg][q*4+0] = ss.x; shQ[rg][q*4+1] = ss.y; shQ[rg][q*4+2] = ss.z; shQ[rg][q*4+3] = ss.w;
    __syncthreads();
    if (threadIdx.x < D) {
        float a = 0.f, c = 0.f;
        #pragma unroll
        for (int g = 0; g < 8; g++) { a += shS[g][threadIdx.x]; c += shQ[g][threadIdx.x]; }
        atomicAdd(&g_sum[threadIdx.x], a);
        atomicAdd(&g_sq[threadIdx.x],  c);
    }
}

// ---------------- 9) BN stats ----------------
__global__ void bnstats_kernel(const float* __restrict__ gamma,
                               const float* __restrict__ beta, float Ninv) {
    int i = threadIdx.x;
    float mean = g_sum[i] * Ninv;
    float var  = fmaxf(g_sq[i] * Ninv - mean * mean, 0.f);
    float istd = rsqrtf(var + BN_EPS);
    float sc = gamma[i] * istd;
    g_scale[i] = sc;
    g_shift[i] = beta[i] - mean * sc;
}

// ---------------- 10) normalize ----------------
__global__ void normalize_kernel(float4* __restrict__ y, int total4) {
    int t = blockIdx.x * blockDim.x + threadIdx.x;
    if (t >= total4) return;
    int cb = (t & 31) * 4;
    float4 v = y[t];
    v.x = fmaf(v.x, g_scale[cb + 0], g_shift[cb + 0]);
    v.y = fmaf(v.y, g_scale[cb + 1], g_shift[cb + 1]);
    v.z = fmaf(v.z, g_scale[cb + 2], g_shift[cb + 2]);
    v.w = fmaf(v.w, g_scale[cb + 3], g_shift[cb + 3]);
    y[t] = v;
}

// ---------------- launch ----------------
extern "C" void kernel_launch(void* const* d_in, const int* in_sizes, int n_in,
                              void* d_out, int out_size) {
    const float* x     = (const float*)d_in[0];
    const int*   src   = (const int*)d_in[1];
    const int*   dst   = (const int*)d_in[2];
    const float* W     = (const float*)d_in[3];
    const float* b     = (const float*)d_in[4];
    const float* Wr    = (const float*)d_in[5];
    const float* br    = (const float*)d_in[6];
    const float* gamma = (const float*)d_in[7];
    const float* beta  = (const float*)d_in[8];
    float* out = (float*)d_out;

    int N  = in_sizes[0] / D;
    int nE = in_sizes[1];
    int n4 = N * D4;

    const int DSMEM = 69632;   // 4 x 64 x 272B
    cudaFuncSetAttribute(gemm_mma_kernel, cudaFuncAttributeMaxDynamicSharedMemorySize, DSMEM);

    zero_kernel<<<(N + 255) / 256, 256>>>(N);
    degree_kernel<<<(nE + 255) / 256, 256>>>(src, dst, nE);
    scan1_kernel<<<SCAN_NB, SCAN_BLK>>>(N);
    scan3_kernel<<<SCAN_NB, SCAN_BLK>>>(N);
    fill_kernel<<<(nE + 255) / 256, 256>>>(src, dst, nE);
    prepw_kernel<<<64, 256>>>(W, Wr);
    {
        long long threads = (long long)N * 32;
        int blocks = (int)((threads + 255) / 256);
        gather_kernel<<<blocks, 256>>>((const float4*)x, N);
    }
    int ntiles = (N + 63) / 64;
    gemm_mma_kernel<<<ntiles, 256, DSMEM>>>((const float4*)x, b, br, out, N);
    bnsum_kernel<<<256, 256>>>((const float4*)out, N);
    bnstats_kernel<<<1, D>>>(gamma, beta, 1.0f / (float)N);
    normalize_kernel<<<(n4 + 255) / 256, 256>>>((float4*)out, n4);
}

// round 10
// speedup vs baseline: 1.2087x; 1.2087x over previous
#include <cuda_runtime.h>
#include <cuda_bf16.h>
#include <cstdint>

#define NMAX 50000
#define EMAX 800000
#define D 128
#define D4 32
#define BN_EPS 1e-5f
#define SCAN_BLK 1024
#define SCAN_NB  49
#define PITCH 272            // bytes per 128-bf16 row (256 + 16 pad)

// ---------------- scratch ----------------
__device__ float4 g_agg[NMAX * D4];
__device__ int    g_deg_out[NMAX];
__device__ int    g_deg_in[NMAX];
__device__ int    g_incl[SCAN_NB * SCAN_BLK];
__device__ int    g_bsum[SCAN_NB];
__device__ int    g_rowstart[NMAX];
__device__ int    g_cursor[NMAX];
__device__ int    g_csrc[EMAX];
__device__ float  g_inv_in[NMAX];
__device__ float  g_inv_out[NMAX];
__device__ float  g_sum[D];
__device__ float  g_sq[D];
__device__ __nv_bfloat16 g_Whi[16384], g_Wlo[16384], g_Wrhi[16384], g_Wrlo[16384];

// ---------------- helpers ----------------
__device__ __forceinline__ uint32_t smem_u32(const void* p) {
    uint32_t a;
    asm("{ .reg .u64 t; cvta.to.shared.u64 t, %1; cvt.u32.u64 %0, t; }" : "=r"(a) : "l"(p));
    return a;
}
__device__ __forceinline__ uint32_t lds32(uint32_t a) {
    uint32_t v;
    asm volatile("ld.shared.b32 %0, [%1];" : "=r"(v) : "r"(a));
    return v;
}
__device__ __forceinline__ void sts128(uint32_t a, uint4 v) {
    asm volatile("st.shared.v4.b32 [%0], {%1,%2,%3,%4};"
                 :: "r"(a), "r"(v.x), "r"(v.y), "r"(v.z), "r"(v.w) : "memory");
}
__device__ __forceinline__ void mma_bf16(float* d, const uint32_t* a, uint32_t b0, uint32_t b1) {
    asm volatile(
        "mma.sync.aligned.m16n8k16.row.col.f32.bf16.bf16.f32 "
        "{%0,%1,%2,%3}, {%4,%5,%6,%7}, {%8,%9}, {%0,%1,%2,%3};"
        : "+f"(d[0]), "+f"(d[1]), "+f"(d[2]), "+f"(d[3])
        : "r"(a[0]), "r"(a[1]), "r"(a[2]), "r"(a[3]), "r"(b0), "r"(b1));
}
__device__ __forceinline__ void splitstore(float v, __nv_bfloat16* hi, __nv_bfloat16* lo) {
    __nv_bfloat16 h = __float2bfloat16_rn(v);
    *hi = h;
    *lo = __float2bfloat16_rn(v - __bfloat162float(h));
}

// ---------------- 1) zero ----------------
__global__ void zero_kernel(int N) {
    int i = blockIdx.x * blockDim.x + threadIdx.x;
    if (i < N) { g_deg_out[i] = 0; g_deg_in[i] = 0; }
    if (i < D) { g_sum[i] = 0.f; g_sq[i] = 0.f; }
}

// ---------------- 2) degrees ----------------
__global__ void degree_kernel(const int* __restrict__ src,
                              const int* __restrict__ dst, int nE) {
    int e = blockIdx.x * blockDim.x + threadIdx.x;
    if (e < nE) {
        atomicAdd(&g_deg_out[src[e]], 1);
        atomicAdd(&g_deg_in[dst[e]], 1);
    }
}

// ---------------- 3a) per-block inclusive scan (warp-shuffle) ----------------
__global__ void scan1_kernel(int N) {
    __shared__ int wsum[32];
    int t = threadIdx.x, lane = t & 31, w = t >> 5;
    int i = blockIdx.x * SCAN_BLK + t;
    int v = (i < N) ? g_deg_in[i] : 0;
    int s = v;
    #pragma unroll
    for (int off = 1; off < 32; off <<= 1) {
        int u = __shfl_up_sync(0xffffffffu, s, off);
        if (lane >= off) s += u;
    }
    if (lane == 31) wsum[w] = s;
    __syncthreads();
    if (w == 0) {
        int ws = wsum[lane];
        #pragma unroll
        for (int off = 1; off < 32; off <<= 1) {
            int u = __shfl_up_sync(0xffffffffu, ws, off);
            if (lane >= off) ws += u;
        }
        wsum[lane] = ws;
    }
    __syncthreads();
    int add = (w > 0) ? wsum[w - 1] : 0;
    g_incl[i] = s + add;
    if (t == SCAN_BLK - 1) g_bsum[blockIdx.x] = s + add;
}

// ---------------- 3b) finalize (block offset inline) ----------------
__global__ void scan3_kernel(int N) {
    __shared__ int s_off;
    if (threadIdx.x < 32) {
        int lane = threadIdx.x;
        int v = 0;
        if (lane < blockIdx.x) v += g_bsum[lane];
        int l2 = lane + 32;
        if (l2 < SCAN_NB && l2 < blockIdx.x) v += g_bsum[l2];
        #pragma unroll
        for (int off = 16; off > 0; off >>= 1)
            v += __shfl_down_sync(0xffffffffu, v, off);
        if (lane == 0) s_off = v;
    }
    __syncthreads();
    int i = blockIdx.x * SCAN_BLK + threadIdx.x;
    if (i >= N) return;
    int din = g_deg_in[i];
    int rs = g_incl[i] - din + s_off;
    g_rowstart[i] = rs;
    g_cursor[i]   = rs;
    g_inv_in[i]  = rsqrtf(fmaxf((float)din, 1.f));
    g_inv_out[i] = rsqrtf(fmaxf((float)g_deg_out[i], 1.f));
}

// ---------------- 4) CSR fill ----------------
__global__ void fill_kernel(const int* __restrict__ src,
                            const int* __restrict__ dst, int nE) {
    int e = blockIdx.x * blockDim.x + threadIdx.x;
    if (e < nE) {
        int pos = atomicAdd(&g_cursor[dst[e]], 1);
        g_csrc[pos] = src[e];
    }
}

// ---------------- 5) gather ----------------
__global__ void gather_kernel(const float4* __restrict__ x4, int N) {
    int w = (blockIdx.x * blockDim.x + threadIdx.x) >> 5;
    int lane = threadIdx.x & 31;
    if (w >= N) return;
    int start = g_rowstart[w];
    int deg   = g_deg_in[w];
    float4 acc = make_float4(0.f, 0.f, 0.f, 0.f);
    for (int base = 0; base < deg; base += 32) {
        int rem = deg - base;
        int cnt = rem < 32 ? rem : 32;
        int sIdx = 0;
        if (lane < cnt) sIdx = g_csrc[start + base + lane];
        #pragma unroll 4
        for (int j = 0; j < cnt; j++) {
            int s = __shfl_sync(0xffffffffu, sIdx, j);
            float sc = __ldg(&g_inv_out[s]);
            float4 v = x4[s * D4 + lane];
            acc.x = fmaf(v.x, sc, acc.x);
            acc.y = fmaf(v.y, sc, acc.y);
            acc.z = fmaf(v.z, sc, acc.z);
            acc.w = fmaf(v.w, sc, acc.w);
        }
    }
    float inv = g_inv_in[w];
    acc.x *= inv; acc.y *= inv; acc.z *= inv; acc.w *= inv;
    g_agg[w * D4 + lane] = acc;
}

// ---------------- 6) prep weights ([n][k], k contiguous) ----------------
__global__ void prepw_kernel(const float* __restrict__ W, const float* __restrict__ Wr) {
    int t = blockIdx.x * blockDim.x + threadIdx.x;
    if (t >= 16384) return;
    int k = t & 127;
    int n = t >> 7;
    int idx = n * 128 + k;
    splitstore(W[k * D + n],  &g_Whi[idx],  &g_Wlo[idx]);
    splitstore(Wr[k * D + n], &g_Wrhi[idx], &g_Wrlo[idx]);
}

// ---------------- 7) HMMA dual GEMM + relu + residual (R6-verified) -----------
__device__ __forceinline__ void compute_phase(
    uint32_t aHi, uint32_t aLo, uint32_t bHi, uint32_t bLo,
    float acc[2][8][4], int warpRow, int warpCol, int gID, int tig)
{
    for (int ks = 0; ks < 8; ks++) {
        uint32_t kb = (uint32_t)(ks * 32 + tig * 4);
        uint32_t ahi[2][4], alo[2][4];
        #pragma unroll
        for (int rt = 0; rt < 2; rt++) {
            uint32_t r0 = (uint32_t)(warpRow + rt * 16 + gID);
            uint32_t b0 = r0 * PITCH + kb;
            ahi[rt][0] = lds32(aHi + b0);
            ahi[rt][1] = lds32(aHi + b0 + 8 * PITCH);
            ahi[rt][2] = lds32(aHi + b0 + 16);
            ahi[rt][3] = lds32(aHi + b0 + 8 * PITCH + 16);
            alo[rt][0] = lds32(aLo + b0);
            alo[rt][1] = lds32(aLo + b0 + 8 * PITCH);
            alo[rt][2] = lds32(aLo + b0 + 16);
            alo[rt][3] = lds32(aLo + b0 + 8 * PITCH + 16);
        }
        #pragma unroll
        for (int nt = 0; nt < 8; nt++) {
            uint32_t n0 = (uint32_t)(warpCol + nt * 8 + gID);
            uint32_t bb = n0 * PITCH + kb;
            uint32_t bh0 = lds32(bHi + bb), bh1 = lds32(bHi + bb + 16);
            uint32_t bl0 = lds32(bLo + bb), bl1 = lds32(bLo + bb + 16);
            #pragma unroll
            for (int rt = 0; rt < 2; rt++) {
                mma_bf16(acc[rt][nt], ahi[rt], bh0, bh1);
                mma_bf16(acc[rt][nt], ahi[rt], bl0, bl1);
                mma_bf16(acc[rt][nt], alo[rt], bh0, bh1);
            }
        }
    }
}

__global__ void __launch_bounds__(256, 1)
gemm_mma_kernel(const float4* __restrict__ x4,
                const float* __restrict__ b, const float* __restrict__ br,
                float* __restrict__ y, int N) {
    extern __shared__ char dsm[];
    uint32_t base = smem_u32(dsm);
    const uint32_t A_HI = base,            A_LO = base + 34816u;
    const uint32_t W_HI = base + 69632u,   W_LO = base + 104448u;
    const uint32_t WR_HI = base + 139264u, WR_LO = base + 174080u;

    __shared__ float sb[D], sbr[D];

    int tid = threadIdx.x;
    int lane = tid & 31, warp = tid >> 5;
    int gID = lane >> 2, tig = lane & 3;
    int warpRow = (warp >> 1) * 32;
    int warpCol = (warp & 1) * 64;
    int rowbase = blockIdx.x * 128;

    if (tid < D) { sb[tid] = b[tid]; sbr[tid] = br[tid]; }

    {
        const uint4* s0 = (const uint4*)g_Whi;  const uint4* s1 = (const uint4*)g_Wlo;
        const uint4* s2 = (const uint4*)g_Wrhi; const uint4* s3 = (const uint4*)g_Wrlo;
        #pragma unroll
        for (int i = tid; i < 2048; i += 256) {
            uint32_t n = (uint32_t)(i >> 4), ci = (uint32_t)(i & 15);
            uint32_t off = n * PITCH + ci * 16;
            sts128(W_HI + off, s0[i]);
            sts128(W_LO + off, s1[i]);
            sts128(WR_HI + off, s2[i]);
            sts128(WR_LO + off, s3[i]);
        }
    }

    // ---- phase 1: A = agg ----
    #pragma unroll
    for (int i = tid; i < 2048; i += 256) {
        int row = i >> 4, ch = i & 15;
        int gr = rowbase + row;
        float4 v0 = make_float4(0.f,0.f,0.f,0.f), v1 = v0;
        if (gr < N) { v0 = g_agg[gr * D4 + ch * 2]; v1 = g_agg[gr * D4 + ch * 2 + 1]; }
        __nv_bfloat16 hi[8], lo[8];
        splitstore(v0.x, hi+0, lo+0); splitstore(v0.y, hi+1, lo+1);
        splitstore(v0.z, hi+2, lo+2); splitstore(v0.w, hi+3, lo+3);
        splitstore(v1.x, hi+4, lo+4); splitstore(v1.y, hi+5, lo+5);
        splitstore(v1.z, hi+6, lo+6); splitstore(v1.w, hi+7, lo+7);
        uint32_t off = (uint32_t)row * PITCH + (uint32_t)ch * 16;
        sts128(A_HI + off, *(const uint4*)hi);
        sts128(A_LO + off, *(const uint4*)lo);
    }
    __syncthreads();

    float accG[2][8][4];
    #pragma unroll
    for (int rt = 0; rt < 2; rt++)
        #pragma unroll
        for (int nt = 0; nt < 8; nt++)
            #pragma unroll
            for (int j = 0; j < 4; j++) accG[rt][nt][j] = 0.f;

    compute_phase(A_HI, A_LO, W_HI, W_LO, accG, warpRow, warpCol, gID, tig);
    __syncthreads();

    // ---- phase 2: A = x ----
    #pragma unroll
    for (int i = tid; i < 2048; i += 256) {
        int row = i >> 4, ch = i & 15;
        int gr = rowbase + row;
        float4 v0 = make_float4(0.f,0.f,0.f,0.f), v1 = v0;
        if (gr < N) { v0 = x4[gr * D4 + ch * 2]; v1 = x4[gr * D4 + ch * 2 + 1]; }
        __nv_bfloat16 hi[8], lo[8];
        splitstore(v0.x, hi+0, lo+0); splitstore(v0.y, hi+1, lo+1);
        splitstore(v0.z, hi+2, lo+2); splitstore(v0.w, hi+3, lo+3);
        splitstore(v1.x, hi+4, lo+4); splitstore(v1.y, hi+5, lo+5);
        splitstore(v1.z, hi+6, lo+6); splitstore(v1.w, hi+7, lo+7);
        uint32_t off = (uint32_t)row * PITCH + (uint32_t)ch * 16;
        sts128(A_HI + off, *(const uint4*)hi);
        sts128(A_LO + off, *(const uint4*)lo);
    }
    __syncthreads();

    float accR[2][8][4];
    #pragma unroll
    for (int rt = 0; rt < 2; rt++)
        #pragma unroll
        for (int nt = 0; nt < 8; nt++)
            #pragma unroll
            for (int j = 0; j < 4; j++) accR[rt][nt][j] = 0.f;

    compute_phase(A_HI, A_LO, WR_HI, WR_LO, accR, warpRow, warpCol, gID, tig);

    // ---- epilogue: y = relu(G+b) + relu(R+br) ----
    #pragma unroll
    for (int rt = 0; rt < 2; rt++) {
        int gr0 = rowbase + warpRow + rt * 16 + gID;
        int gr1 = gr0 + 8;
        #pragma unroll
        for (int nt = 0; nt < 8; nt++) {
            int c0 = warpCol + nt * 8 + tig * 2;
            float bx = sb[c0], by = sb[c0 + 1];
            float brx = sbr[c0], bry = sbr[c0 + 1];
            if (gr0 < N) {
                float2 o;
                o.x = fmaxf(accG[rt][nt][0] + bx, 0.f) + fmaxf(accR[rt][nt][0] + brx, 0.f);
                o.y = fmaxf(accG[rt][nt][1] + by, 0.f) + fmaxf(accR[rt][nt][1] + bry, 0.f);
                *(float2*)(y + gr0 * D + c0) = o;
            }
            if (gr1 < N) {
                float2 o;
                o.x = fmaxf(accG[rt][nt][2] + bx, 0.f) + fmaxf(accR[rt][nt][2] + brx, 0.f);
                o.y = fmaxf(accG[rt][nt][3] + by, 0.f) + fmaxf(accR[rt][nt][3] + bry, 0.f);
                *(float2*)(y + gr1 * D + c0) = o;
            }
        }
    }
}

// ---------------- 8) BN column sums ----------------
__global__ void bnsum_kernel(const float4* __restrict__ y4, int N) {
    int q = threadIdx.x & 31, rg = threadIdx.x >> 5;
    float4 s  = make_float4(0.f,0.f,0.f,0.f);
    float4 ss = make_float4(0.f,0.f,0.f,0.f);
    for (int r = blockIdx.x * 8 + rg; r < N; r += gridDim.x * 8) {
        float4 v = y4[r * D4 + q];
        s.x += v.x; s.y += v.y; s.z += v.z; s.w += v.w;
        ss.x += v.x*v.x; ss.y += v.y*v.y; ss.z += v.z*v.z; ss.w += v.w*v.w;
    }
    __shared__ float shS[8][D], shQ[8][D];
    shS[rg][q*4+0] = s.x;  shS[rg][q*4+1] = s.y;  shS[rg][q*4+2] = s.z;  shS[rg][q*4+3] = s.w;
    shQ[rg][q*4+0] = ss.x; shQ[rg][q*4+1] = ss.y; shQ[rg][q*4+2] = ss.z; shQ[rg][q*4+3] = ss.w;
    __syncthreads();
    if (threadIdx.x < D) {
        float a = 0.f, c = 0.f;
        #pragma unroll
        for (int g = 0; g < 8; g++) { a += shS[g][threadIdx.x]; c += shQ[g][threadIdx.x]; }
        atomicAdd(&g_sum[threadIdx.x], a);
        atomicAdd(&g_sq[threadIdx.x],  c);
    }
}

// ---------------- 9) normalize (BN stats computed inline) ----------------
__global__ void normalize_kernel(float4* __restrict__ y,
                                 const float* __restrict__ gamma,
                                 const float* __restrict__ beta,
                                 float Ninv, int total4) {
    int t = blockIdx.x * blockDim.x + threadIdx.x;
    if (t >= total4) return;
    int cb = (t & 31) * 4;
    float4 sc, sh;
    #pragma unroll
    for (int j = 0; j < 4; j++) {
        int c = cb + j;
        float mean = g_sum[c] * Ninv;
        float var  = fmaxf(g_sq[c] * Ninv - mean * mean, 0.f);
        float istd = rsqrtf(var + BN_EPS);
        float s = __ldg(&gamma[c]) * istd;
        ((float*)&sc)[j] = s;
        ((float*)&sh)[j] = __ldg(&beta[c]) - mean * s;
    }
    float4 v = y[t];
    v.x = fmaf(v.x, sc.x, sh.x);
    v.y = fmaf(v.y, sc.y, sh.y);
    v.z = fmaf(v.z, sc.z, sh.z);
    v.w = fmaf(v.w, sc.w, sh.w);
    y[t] = v;
}

// ---------------- launch ----------------
extern "C" void kernel_launch(void* const* d_in, const int* in_sizes, int n_in,
                              void* d_out, int out_size) {
    const float* x     = (const float*)d_in[0];
    const int*   src   = (const int*)d_in[1];
    const int*   dst   = (const int*)d_in[2];
    const float* W     = (const float*)d_in[3];
    const float* b     = (const float*)d_in[4];
    const float* Wr    = (const float*)d_in[5];
    const float* br    = (const float*)d_in[6];
    const float* gamma = (const float*)d_in[7];
    const float* beta  = (const float*)d_in[8];
    float* out = (float*)d_out;

    int N  = in_sizes[0] / D;
    int nE = in_sizes[1];
    int n4 = N * D4;

    const int DSMEM = 208896;
    cudaFuncSetAttribute(gemm_mma_kernel, cudaFuncAttributeMaxDynamicSharedMemorySize, DSMEM);

    zero_kernel<<<(N + 255) / 256, 256>>>(N);
    degree_kernel<<<(nE + 255) / 256, 256>>>(src, dst, nE);
    scan1_kernel<<<SCAN_NB, SCAN_BLK>>>(N);
    scan3_kernel<<<SCAN_NB, SCAN_BLK>>>(N);
    fill_kernel<<<(nE + 255) / 256, 256>>>(src, dst, nE);
    prepw_kernel<<<64, 256>>>(W, Wr);
    {
        long long threads = (long long)N * 32;
        int blocks = (int)((threads + 255) / 256);
        gather_kernel<<<blocks, 256>>>((const float4*)x, N);
    }
    int ntiles = (N + 127) / 128;
    gemm_mma_kernel<<<ntiles, 256, DSMEM>>>((const float4*)x, b, br, out, N);
    bnsum_kernel<<<256, 256>>>((const float4*)out, N);
    normalize_kernel<<<(n4 + 255) / 256, 256>>>((float4*)out, gamma, beta,
                                                1.0f / (float)N, n4);
}

// round 15
// speedup vs baseline: 1.2738x; 1.0539x over previous
#include <cuda_runtime.h>
#include <cuda_bf16.h>
#include <cstdint>

#define NMAX 50000
#define EMAX 800000
#define D 128
#define D4 32
#define BN_EPS 1e-5f
#define SCAN_BLK 1024
#define SCAN_NB  49
#define PITCH 272            // bytes per 128-bf16 row (256 + 16 pad)

// ---------------- scratch ----------------
__device__ float4 g_agg[NMAX * D4];
__device__ int    g_deg_out[NMAX];
__device__ int    g_deg_in[NMAX];
__device__ int    g_incl[SCAN_NB * SCAN_BLK];
__device__ int    g_bsum[SCAN_NB];
__device__ int    g_rowstart[NMAX];
__device__ int    g_cursor[NMAX];
__device__ int    g_csrc[EMAX];
__device__ float  g_inv_in[NMAX];
__device__ float  g_inv_out[NMAX];
__device__ float  g_sum[D];
__device__ float  g_sq[D];
__device__ float  g_scale[D];
__device__ float  g_shift[D];
__device__ __nv_bfloat16 g_Whi[16384], g_Wlo[16384], g_Wrhi[16384], g_Wrlo[16384];

// ---------------- helpers ----------------
__device__ __forceinline__ uint32_t smem_u32(const void* p) {
    uint32_t a;
    asm("{ .reg .u64 t; cvta.to.shared.u64 t, %1; cvt.u32.u64 %0, t; }" : "=r"(a) : "l"(p));
    return a;
}
__device__ __forceinline__ uint32_t lds32(uint32_t a) {
    uint32_t v;
    asm volatile("ld.shared.b32 %0, [%1];" : "=r"(v) : "r"(a));
    return v;
}
__device__ __forceinline__ void sts128(uint32_t a, uint4 v) {
    asm volatile("st.shared.v4.b32 [%0], {%1,%2,%3,%4};"
                 :: "r"(a), "r"(v.x), "r"(v.y), "r"(v.z), "r"(v.w) : "memory");
}
__device__ __forceinline__ void mma_bf16(float* d, const uint32_t* a, uint32_t b0, uint32_t b1) {
    asm volatile(
        "mma.sync.aligned.m16n8k16.row.col.f32.bf16.bf16.f32 "
        "{%0,%1,%2,%3}, {%4,%5,%6,%7}, {%8,%9}, {%0,%1,%2,%3};"
        : "+f"(d[0]), "+f"(d[1]), "+f"(d[2]), "+f"(d[3])
        : "r"(a[0]), "r"(a[1]), "r"(a[2]), "r"(a[3]), "r"(b0), "r"(b1));
}
__device__ __forceinline__ void splitstore(float v, __nv_bfloat16* hi, __nv_bfloat16* lo) {
    __nv_bfloat16 h = __float2bfloat16_rn(v);
    *hi = h;
    *lo = __float2bfloat16_rn(v - __bfloat162float(h));
}

// ---------------- 1) zero ----------------
__global__ void zero_kernel(int N) {
    int i = blockIdx.x * blockDim.x + threadIdx.x;
    if (i < N) { g_deg_out[i] = 0; g_deg_in[i] = 0; }
    if (i < D) { g_sum[i] = 0.f; g_sq[i] = 0.f; }
}

// ---------------- 2) degrees ----------------
__global__ void degree_kernel(const int* __restrict__ src,
                              const int* __restrict__ dst, int nE) {
    int e = blockIdx.x * blockDim.x + threadIdx.x;
    if (e < nE) {
        atomicAdd(&g_deg_out[src[e]], 1);
        atomicAdd(&g_deg_in[dst[e]], 1);
    }
}

// ---------------- 3a) per-block inclusive scan (warp-shuffle) ----------------
__global__ void scan1_kernel(int N) {
    __shared__ int wsum[32];
    int t = threadIdx.x, lane = t & 31, w = t >> 5;
    int i = blockIdx.x * SCAN_BLK + t;
    int v = (i < N) ? g_deg_in[i] : 0;
    int s = v;
    #pragma unroll
    for (int off = 1; off < 32; off <<= 1) {
        int u = __shfl_up_sync(0xffffffffu, s, off);
        if (lane >= off) s += u;
    }
    if (lane == 31) wsum[w] = s;
    __syncthreads();
    if (w == 0) {
        int ws = wsum[lane];
        #pragma unroll
        for (int off = 1; off < 32; off <<= 1) {
            int u = __shfl_up_sync(0xffffffffu, ws, off);
            if (lane >= off) ws += u;
        }
        wsum[lane] = ws;
    }
    __syncthreads();
    int add = (w > 0) ? wsum[w - 1] : 0;
    g_incl[i] = s + add;
    if (t == SCAN_BLK - 1) g_bsum[blockIdx.x] = s + add;
}

// ---------------- 3b) finalize (block offset inline) ----------------
__global__ void scan3_kernel(int N) {
    __shared__ int s_off;
    if (threadIdx.x < 32) {
        int lane = threadIdx.x;
        int v = 0;
        if (lane < blockIdx.x) v += g_bsum[lane];
        int l2 = lane + 32;
        if (l2 < SCAN_NB && l2 < blockIdx.x) v += g_bsum[l2];
        #pragma unroll
        for (int off = 16; off > 0; off >>= 1)
            v += __shfl_down_sync(0xffffffffu, v, off);
        if (lane == 0) s_off = v;
    }
    __syncthreads();
    int i = blockIdx.x * SCAN_BLK + threadIdx.x;
    if (i >= N) return;
    int din = g_deg_in[i];
    int rs = g_incl[i] - din + s_off;
    g_rowstart[i] = rs;
    g_cursor[i]   = rs;
    g_inv_in[i]  = rsqrtf(fmaxf((float)din, 1.f));
    g_inv_out[i] = rsqrtf(fmaxf((float)g_deg_out[i], 1.f));
}

// ---------------- 4) CSR fill ----------------
__global__ void fill_kernel(const int* __restrict__ src,
                            const int* __restrict__ dst, int nE) {
    int e = blockIdx.x * blockDim.x + threadIdx.x;
    if (e < nE) {
        int pos = atomicAdd(&g_cursor[dst[e]], 1);
        g_csrc[pos] = src[e];
    }
}

// ---------------- 5) gather ----------------
__global__ void gather_kernel(const float4* __restrict__ x4, int N) {
    int w = (blockIdx.x * blockDim.x + threadIdx.x) >> 5;
    int lane = threadIdx.x & 31;
    if (w >= N) return;
    int start = g_rowstart[w];
    int deg   = g_deg_in[w];
    float4 acc = make_float4(0.f, 0.f, 0.f, 0.f);
    for (int base = 0; base < deg; base += 32) {
        int rem = deg - base;
        int cnt = rem < 32 ? rem : 32;
        int sIdx = 0;
        if (lane < cnt) sIdx = g_csrc[start + base + lane];
        #pragma unroll 4
        for (int j = 0; j < cnt; j++) {
            int s = __shfl_sync(0xffffffffu, sIdx, j);
            float sc = __ldg(&g_inv_out[s]);
            float4 v = x4[s * D4 + lane];
            acc.x = fmaf(v.x, sc, acc.x);
            acc.y = fmaf(v.y, sc, acc.y);
            acc.z = fmaf(v.z, sc, acc.z);
            acc.w = fmaf(v.w, sc, acc.w);
        }
    }
    float inv = g_inv_in[w];
    acc.x *= inv; acc.y *= inv; acc.z *= inv; acc.w *= inv;
    g_agg[w * D4 + lane] = acc;
}

// ---------------- 6) prep weights ([n][k], k contiguous) ----------------
__global__ void prepw_kernel(const float* __restrict__ W, const float* __restrict__ Wr) {
    int t = blockIdx.x * blockDim.x + threadIdx.x;
    if (t >= 16384) return;
    int k = t & 127;
    int n = t >> 7;
    int idx = n * 128 + k;
    splitstore(W[k * D + n],  &g_Whi[idx],  &g_Wlo[idx]);
    splitstore(Wr[k * D + n], &g_Wrhi[idx], &g_Wrlo[idx]);
}

// ---------------- 7) persistent HMMA dual GEMM + relu + residual --------------
__device__ __forceinline__ void compute_phase(
    uint32_t aHi, uint32_t aLo, uint32_t bHi, uint32_t bLo,
    float acc[2][8][4], int warpRow, int warpCol, int gID, int tig)
{
    for (int ks = 0; ks < 8; ks++) {
        uint32_t kb = (uint32_t)(ks * 32 + tig * 4);
        uint32_t ahi[2][4], alo[2][4];
        #pragma unroll
        for (int rt = 0; rt < 2; rt++) {
            uint32_t r0 = (uint32_t)(warpRow + rt * 16 + gID);
            uint32_t b0 = r0 * PITCH + kb;
            ahi[rt][0] = lds32(aHi + b0);
            ahi[rt][1] = lds32(aHi + b0 + 8 * PITCH);
            ahi[rt][2] = lds32(aHi + b0 + 16);
            ahi[rt][3] = lds32(aHi + b0 + 8 * PITCH + 16);
            alo[rt][0] = lds32(aLo + b0);
            alo[rt][1] = lds32(aLo + b0 + 8 * PITCH);
            alo[rt][2] = lds32(aLo + b0 + 16);
            alo[rt][3] = lds32(aLo + b0 + 8 * PITCH + 16);
        }
        #pragma unroll
        for (int nt = 0; nt < 8; nt++) {
            uint32_t n0 = (uint32_t)(warpCol + nt * 8 + gID);
            uint32_t bb = n0 * PITCH + kb;
            uint32_t bh0 = lds32(bHi + bb), bh1 = lds32(bHi + bb + 16);
            uint32_t bl0 = lds32(bLo + bb), bl1 = lds32(bLo + bb + 16);
            #pragma unroll
            for (int rt = 0; rt < 2; rt++) {
                mma_bf16(acc[rt][nt], ahi[rt], bh0, bh1);
                mma_bf16(acc[rt][nt], ahi[rt], bl0, bl1);
                mma_bf16(acc[rt][nt], alo[rt], bh0, bh1);
            }
        }
    }
}

__global__ void __launch_bounds__(256, 1)
gemm_mma_kernel(const float4* __restrict__ x4,
                const float* __restrict__ b, const float* __restrict__ br,
                float* __restrict__ y, int N, int ntiles) {
    extern __shared__ char dsm[];
    uint32_t base = smem_u32(dsm);
    const uint32_t A_HI = base,            A_LO = base + 34816u;
    const uint32_t W_HI = base + 69632u,   W_LO = base + 104448u;
    const uint32_t WR_HI = base + 139264u, WR_LO = base + 174080u;

    __shared__ float sb[D], sbr[D];

    int tid = threadIdx.x;
    int lane = tid & 31, warp = tid >> 5;
    int gID = lane >> 2, tig = lane & 3;
    int warpRow = (warp >> 1) * 32;
    int warpCol = (warp & 1) * 64;

    if (tid < D) { sb[tid] = b[tid]; sbr[tid] = br[tid]; }

    // stage weights ONCE per CTA
    {
        const uint4* s0 = (const uint4*)g_Whi;  const uint4* s1 = (const uint4*)g_Wlo;
        const uint4* s2 = (const uint4*)g_Wrhi; const uint4* s3 = (const uint4*)g_Wrlo;
        #pragma unroll
        for (int i = tid; i < 2048; i += 256) {
            uint32_t n = (uint32_t)(i >> 4), ci = (uint32_t)(i & 15);
            uint32_t off = n * PITCH + ci * 16;
            sts128(W_HI + off, s0[i]);
            sts128(W_LO + off, s1[i]);
            sts128(WR_HI + off, s2[i]);
            sts128(WR_LO + off, s3[i]);
        }
    }

    for (int tile = blockIdx.x; tile < ntiles; tile += gridDim.x) {
        int rowbase = tile * 128;
        __syncthreads();   // weights staged / previous tile's compute done

        // ---- phase 1: A = agg ----
        #pragma unroll
        for (int i = tid; i < 2048; i += 256) {
            int row = i >> 4, ch = i & 15;
            int gr = rowbase + row;
            float4 v0 = make_float4(0.f,0.f,0.f,0.f), v1 = v0;
            if (gr < N) { v0 = g_agg[gr * D4 + ch * 2]; v1 = g_agg[gr * D4 + ch * 2 + 1]; }
            __nv_bfloat16 hi[8], lo[8];
            splitstore(v0.x, hi+0, lo+0); splitstore(v0.y, hi+1, lo+1);
            splitstore(v0.z, hi+2, lo+2); splitstore(v0.w, hi+3, lo+3);
            splitstore(v1.x, hi+4, lo+4); splitstore(v1.y, hi+5, lo+5);
            splitstore(v1.z, hi+6, lo+6); splitstore(v1.w, hi+7, lo+7);
            uint32_t off = (uint32_t)row * PITCH + (uint32_t)ch * 16;
            sts128(A_HI + off, *(const uint4*)hi);
            sts128(A_LO + off, *(const uint4*)lo);
        }
        __syncthreads();

        float accG[2][8][4];
        #pragma unroll
        for (int rt = 0; rt < 2; rt++)
            #pragma unroll
            for (int nt = 0; nt < 8; nt++)
                #pragma unroll
                for (int j = 0; j < 4; j++) accG[rt][nt][j] = 0.f;

        compute_phase(A_HI, A_LO, W_HI, W_LO, accG, warpRow, warpCol, gID, tig);
        __syncthreads();

        // ---- phase 2: A = x ----
        #pragma unroll
        for (int i = tid; i < 2048; i += 256) {
            int row = i >> 4, ch = i & 15;
            int gr = rowbase + row;
            float4 v0 = make_float4(0.f,0.f,0.f,0.f), v1 = v0;
            if (gr < N) { v0 = x4[gr * D4 + ch * 2]; v1 = x4[gr * D4 + ch * 2 + 1]; }
            __nv_bfloat16 hi[8], lo[8];
            splitstore(v0.x, hi+0, lo+0); splitstore(v0.y, hi+1, lo+1);
            splitstore(v0.z, hi+2, lo+2); splitstore(v0.w, hi+3, lo+3);
            splitstore(v1.x, hi+4, lo+4); splitstore(v1.y, hi+5, lo+5);
            splitstore(v1.z, hi+6, lo+6); splitstore(v1.w, hi+7, lo+7);
            uint32_t off = (uint32_t)row * PITCH + (uint32_t)ch * 16;
            sts128(A_HI + off, *(const uint4*)hi);
            sts128(A_LO + off, *(const uint4*)lo);
        }
        __syncthreads();

        float accR[2][8][4];
        #pragma unroll
        for (int rt = 0; rt < 2; rt++)
            #pragma unroll
            for (int nt = 0; nt < 8; nt++)
                #pragma unroll
                for (int j = 0; j < 4; j++) accR[rt][nt][j] = 0.f;

        compute_phase(A_HI, A_LO, WR_HI, WR_LO, accR, warpRow, warpCol, gID, tig);

        // ---- epilogue: y = relu(G+b) + relu(R+br) ----
        #pragma unroll
        for (int rt = 0; rt < 2; rt++) {
            int gr0 = rowbase + warpRow + rt * 16 + gID;
            int gr1 = gr0 + 8;
            #pragma unroll
            for (int nt = 0; nt < 8; nt++) {
                int c0 = warpCol + nt * 8 + tig * 2;
                float bx = sb[c0], by = sb[c0 + 1];
                float brx = sbr[c0], bry = sbr[c0 + 1];
                if (gr0 < N) {
                    float2 o;
                    o.x = fmaxf(accG[rt][nt][0] + bx, 0.f) + fmaxf(accR[rt][nt][0] + brx, 0.f);
                    o.y = fmaxf(accG[rt][nt][1] + by, 0.f) + fmaxf(accR[rt][nt][1] + bry, 0.f);
                    *(float2*)(y + gr0 * D + c0) = o;
                }
                if (gr1 < N) {
                    float2 o;
                    o.x = fmaxf(accG[rt][nt][2] + bx, 0.f) + fmaxf(accR[rt][nt][2] + brx, 0.f);
                    o.y = fmaxf(accG[rt][nt][3] + by, 0.f) + fmaxf(accR[rt][nt][3] + bry, 0.f);
                    *(float2*)(y + gr1 * D + c0) = o;
                }
            }
        }
    }
}

// ---------------- 8) BN column sums ----------------
__global__ void bnsum_kernel(const float4* __restrict__ y4, int N) {
    int q = threadIdx.x & 31, rg = threadIdx.x >> 5;
    float4 s  = make_float4(0.f,0.f,0.f,0.f);
    float4 ss = make_float4(0.f,0.f,0.f,0.f);
    for (int r = blockIdx.x * 8 + rg; r < N; r += gridDim.x * 8) {
        float4 v = y4[r * D4 + q];
        s.x += v.x; s.y += v.y; s.z += v.z; s.w += v.w;
        ss.x += v.x*v.x; ss.y += v.y*v.y; ss.z += v.z*v.z; ss.w += v.w*v.w;
    }
    __shared__ float shS[8][D], shQ[8][D];
    shS[rg][q*4+0] = s.x;  shS[rg][q*4+1] = s.y;  shS[rg][q*4+2] = s.z;  shS[rg][q*4+3] = s.w;
    shQ[rg][q*4+0] = ss.x; shQ[rg][q*4+1] = ss.y; shQ[rg][q*4+2] = ss.z; shQ[rg][q*4+3] = ss.w;
    __syncthreads();
    if (threadIdx.x < D) {
        float a = 0.f, c = 0.f;
        #pragma unroll
        for (int g = 0; g < 8; g++) { a += shS[g][threadIdx.x]; c += shQ[g][threadIdx.x]; }
        atomicAdd(&g_sum[threadIdx.x], a);
        atomicAdd(&g_sq[threadIdx.x],  c);
    }
}

// ---------------- 9) BN stats ----------------
__global__ void bnstats_kernel(const float* __restrict__ gamma,
                               const float* __restrict__ beta, float Ninv) {
    int i = threadIdx.x;
    float mean = g_sum[i] * Ninv;
    float var  = fmaxf(g_sq[i] * Ninv - mean * mean, 0.f);
    float istd = rsqrtf(var + BN_EPS);
    float sc = gamma[i] * istd;
    g_scale[i] = sc;
    g_shift[i] = beta[i] - mean * sc;
}

// ---------------- 10) normalize ----------------
__global__ void normalize_kernel(float4* __restrict__ y, int total4) {
    int t = blockIdx.x * blockDim.x + threadIdx.x;
    if (t >= total4) return;
    int cb = (t & 31) * 4;
    float4 v = y[t];
    v.x = fmaf(v.x, g_scale[cb + 0], g_shift[cb + 0]);
    v.y = fmaf(v.y, g_scale[cb + 1], g_shift[cb + 1]);
    v.z = fmaf(v.z, g_scale[cb + 2], g_shift[cb + 2]);
    v.w = fmaf(v.w, g_scale[cb + 3], g_shift[cb + 3]);
    y[t] = v;
}

// ---------------- launch ----------------
extern "C" void kernel_launch(void* const* d_in, const int* in_sizes, int n_in,
                              void* d_out, int out_size) {
    const float* x     = (const float*)d_in[0];
    const int*   src   = (const int*)d_in[1];
    const int*   dst   = (const int*)d_in[2];
    const float* W     = (const float*)d_in[3];
    const float* b     = (const float*)d_in[4];
    const float* Wr    = (const float*)d_in[5];
    const float* br    = (const float*)d_in[6];
    const float* gamma = (const float*)d_in[7];
    const float* beta  = (const float*)d_in[8];
    float* out = (float*)d_out;

    int N  = in_sizes[0] / D;
    int nE = in_sizes[1];
    int n4 = N * D4;

    const int DSMEM = 208896;
    cudaFuncSetAttribute(gemm_mma_kernel, cudaFuncAttributeMaxDynamicSharedMemorySize, DSMEM);

    zero_kernel<<<(N + 255) / 256, 256>>>(N);
    degree_kernel<<<(nE + 255) / 256, 256>>>(src, dst, nE);
    scan1_kernel<<<SCAN_NB, SCAN_BLK>>>(N);
    scan3_kernel<<<SCAN_NB, SCAN_BLK>>>(N);
    fill_kernel<<<(nE + 255) / 256, 256>>>(src, dst, nE);
    prepw_kernel<<<64, 256>>>(W, Wr);
    {
        long long threads = (long long)N * 32;
        int blocks = (int)((threads + 255) / 256);
        gather_kernel<<<blocks, 256>>>((const float4*)x, N);
    }
    int ntiles = (N + 127) / 128;
    int grid = ntiles < 148 ? ntiles : 148;
    gemm_mma_kernel<<<grid, 256, DSMEM>>>((const float4*)x, b, br, out, N, ntiles);
    bnsum_kernel<<<256, 256>>>((const float4*)out, N);
    bnstats_kernel<<<1, D>>>(gamma, beta, 1.0f / (float)N);
    normalize_kernel<<<(n4 + 255) / 256, 256>>>((float4*)out, n4);
}